// round 2
// baseline (speedup 1.0000x reference)
#include <cuda_runtime.h>
#include <cstdint>

#define D        64        // feature dim
#define DP       (D/2)     // packed f32x2 per row
#define TPB      128       // threads per block
#define RPT      2         // rows per thread
#define ROWS_PB  (TPB*RPT) // 256 rows per block
#define TCODES   64        // codes per smem tile

__device__ float g_c2[4096];   // ||code||^2, precomputed

// packed f32x2 FMA: acc = a*b + acc (elementwise on 2 packed fp32)
#define FMA_F32X2(acc, a, b) \
    asm("fma.rn.f32x2 %0, %1, %2, %0;" : "+l"(acc) : "l"(a), "l"(b))

static __device__ __forceinline__ unsigned long long pack2(float lo, float hi) {
    unsigned long long r;
    asm("mov.b64 %0, {%1, %2};" : "=l"(r) : "f"(lo), "f"(hi));
    return r;
}
static __device__ __forceinline__ void unpack2(unsigned long long v, float& lo, float& hi) {
    asm("mov.b64 {%0, %1}, %2;" : "=f"(lo), "=f"(hi) : "l"(v));
}

__global__ void c2_kernel(const float* __restrict__ codes, int M) {
    int m = blockIdx.x * blockDim.x + threadIdx.x;
    if (m < M) {
        const float4* c = reinterpret_cast<const float4*>(codes + (size_t)m * D);
        float s = 0.f;
#pragma unroll
        for (int i = 0; i < D / 4; i++) {
            float4 v = c[i];
            s += v.x * v.x + v.y * v.y + v.z * v.z + v.w * v.w;
        }
        g_c2[m] = s;
    }
}

__global__ __launch_bounds__(TPB) void nn_kernel(
    const float* __restrict__ x,
    const float* __restrict__ codes,
    float* __restrict__ out,          // float32 output! (-1.0f or (float)id)
    int M)   // number of codes
{
    __shared__ float2 sc[TCODES][DP];   // code tile, packed pairs along D
    __shared__ float  sc2[TCODES];      // ||c||^2 tile

    const int t    = threadIdx.x;
    const int row0 = blockIdx.x * ROWS_PB + t;        // first row
    const int row1 = row0 + TPB;                      // second row

    // ---- load both x rows into registers (packed) + compute ||x||^2 ----
    unsigned long long xr0[DP], xr1[DP];
    float x2r0 = 0.f, x2r1 = 0.f;
    {
        const float2* xp0 = reinterpret_cast<const float2*>(x + (size_t)row0 * D);
        const float2* xp1 = reinterpret_cast<const float2*>(x + (size_t)row1 * D);
#pragma unroll
        for (int k = 0; k < DP; k++) {
            float2 v0 = xp0[k];
            float2 v1 = xp1[k];
            xr0[k] = pack2(v0.x, v0.y);
            xr1[k] = pack2(v1.x, v1.y);
            x2r0 += v0.x * v0.x + v0.y * v0.y;
            x2r1 += v1.x * v1.x + v1.y * v1.y;
        }
    }

    float minv0 = 3.4e38f, minv1 = 3.4e38f;
    int   id0 = 0, id1 = 0;

    for (int tile = 0; tile < M; tile += TCODES) {
        __syncthreads();   // previous tile's readers done before overwrite
        // ---- cooperative tile load: TCODES*D floats = 1024 float4 ----
        {
            const float4* gsrc = reinterpret_cast<const float4*>(codes + (size_t)tile * D);
            float4* sdst = reinterpret_cast<float4*>(&sc[0][0]);
#pragma unroll
            for (int i = 0; i < (TCODES * D / 4) / TPB; i++)   // 8 iters
                sdst[t + i * TPB] = gsrc[t + i * TPB];
            if (t < TCODES) sc2[t] = g_c2[tile + t];
        }
        __syncthreads();

#pragma unroll 1
        for (int j = 0; j < TCODES; j++) {
            const unsigned long long* cj =
                reinterpret_cast<const unsigned long long*>(&sc[j][0]);
            // two independent accumulator chains per row (ILP=4 total)
            unsigned long long a0a = 0ull, a0b = 0ull, a1a = 0ull, a1b = 0ull;
#pragma unroll
            for (int k = 0; k < DP; k += 2) {
                unsigned long long c0 = cj[k];
                unsigned long long c1 = cj[k + 1];
                FMA_F32X2(a0a, xr0[k],     c0);
                FMA_F32X2(a1a, xr1[k],     c0);
                FMA_F32X2(a0b, xr0[k + 1], c1);
                FMA_F32X2(a1b, xr1[k + 1], c1);
            }
            float p0, q0, p1, q1, r0x, r0y, r1x, r1y;
            unpack2(a0a, p0, q0); unpack2(a0b, r0x, r0y);
            unpack2(a1a, p1, q1); unpack2(a1b, r1x, r1y);
            float dot0 = (p0 + q0) + (r0x + r0y);
            float dot1 = (p1 + q1) + (r1x + r1y);
            float c2j = sc2[j];
            float s0 = c2j - 2.f * dot0;   // d^2 - ||x||^2 (x^2 is row-constant)
            float s1 = c2j - 2.f * dot1;
            if (s0 < minv0) { minv0 = s0; id0 = tile + j; }
            if (s1 < minv1) { minv1 = s1; id1 = tile + j; }
        }
    }

    // output dtype is float32 (ids cast to float; NO_CODE = -1.0f)
    out[row0] = (minv0 + x2r0 <= 0.1f) ? (float)id0 : -1.0f;
    out[row1] = (minv1 + x2r1 <= 0.1f) ? (float)id1 : -1.0f;
}

extern "C" void kernel_launch(void* const* d_in, const int* in_sizes, int n_in,
                              void* d_out, int out_size) {
    const float* x     = (const float*)d_in[0];
    const float* codes = (const float*)d_in[1];
    float*       out   = (float*)d_out;

    const int M     = in_sizes[1] / D;          // 4096 codes
    const int nRows = in_sizes[0] / D;          // 65536 rows

    c2_kernel<<<(M + 255) / 256, 256>>>(codes, M);
    nn_kernel<<<nRows / ROWS_PB, TPB>>>(x, codes, out, M);
}

// round 4
// speedup vs baseline: 7.1113x; 7.1113x over previous
#include <cuda_runtime.h>
#include <cuda_bf16.h>
#include <cstdint>

#define D        64
#define MT       128         // x rows per CTA
#define NC       64          // codes per chunk
#define TPB      128
#define MAXM     4096

__device__ __align__(16) __nv_bfloat16 g_codes_bf16[MAXM * D];
__device__ __align__(16) float         g_c2s[MAXM];   // ||c||^2 + 256

static __device__ __forceinline__ uint32_t pk(float lo, float hi) {
    uint32_t u;
    asm("cvt.rn.bf16x2.f32 %0, %1, %2;" : "=r"(u) : "f"(hi), "f"(lo));
    return u;
}
static __device__ __forceinline__ uint32_t su32(const void* p) {
    uint32_t a;
    asm("{ .reg .u64 t; cvta.to.shared.u64 t, %1; cvt.u32.u64 %0, t; }" : "=r"(a) : "l"(p));
    return a;
}

#define LDSM4(r0, r1, r2, r3, addr)                                                   \
    asm volatile("ldmatrix.sync.aligned.m8n8.x4.shared.b16 {%0,%1,%2,%3}, [%4];"      \
                 : "=r"(r0), "=r"(r1), "=r"(r2), "=r"(r3) : "r"(addr))

#define MMA16816(c, a, b0, b1)                                                        \
    asm volatile("mma.sync.aligned.m16n8k16.row.col.f32.bf16.bf16.f32 "               \
                 "{%0,%1,%2,%3},{%4,%5,%6,%7},{%8,%9},{%0,%1,%2,%3};"                 \
                 : "+f"((c)[0]), "+f"((c)[1]), "+f"((c)[2]), "+f"((c)[3])             \
                 : "r"((a)[0]), "r"((a)[1]), "r"((a)[2]), "r"((a)[3]),                \
                   "r"(b0), "r"(b1))

#define CPASYNC16(saddr, gptr)                                                        \
    asm volatile("cp.async.cg.shared.global [%0], [%1], 16;" :: "r"(saddr), "l"(gptr))
#define CPCOMMIT() asm volatile("cp.async.commit_group;")
#define CPWAIT(n)  asm volatile("cp.async.wait_group %0;" :: "n"(n))

// ---------------- prep: codes -> bf16 + (||c||^2 + 256) ----------------
__global__ void prep_kernel(const float* __restrict__ codes, int M) {
    int m = blockIdx.x * blockDim.x + threadIdx.x;
    if (m >= M) return;
    const float4* c = reinterpret_cast<const float4*>(codes + (size_t)m * D);
    uint2* dst = reinterpret_cast<uint2*>(g_codes_bf16 + (size_t)m * D);
    float s = 0.f;
#pragma unroll
    for (int i = 0; i < D / 4; i++) {
        float4 v = c[i];
        s += v.x * v.x + v.y * v.y + v.z * v.z + v.w * v.w;
        dst[i] = make_uint2(pk(v.x, v.y), pk(v.z, v.w));
    }
    g_c2s[m] = s + 256.f;    // shift keeps s' = c2s - 2 x.c strictly positive
}

// ---------------- main kernel ----------------
__global__ __launch_bounds__(TPB, 2) void nn_mma_kernel(
    const float* __restrict__ x, float* __restrict__ out, int M)
{
    __shared__ __align__(16) unsigned char sA[MT * 128];       // x tile bf16, swizzled
    __shared__ __align__(16) unsigned char sB[2][NC * 128];    // code chunk double buf
    __shared__ float sx2[MT];

    const int t = threadIdx.x;
    const int L = t & 31;
    const int w = t >> 5;
    const int CHUNKS = M / NC;

    // ---- stage x row t into sA (row t = 128B = 8 chunks of 16B, XOR swizzle) ----
    {
        const float4* xr = reinterpret_cast<const float4*>(
            x + ((size_t)blockIdx.x * MT + t) * D);
        float x2 = 0.f;
#pragma unroll
        for (int i = 0; i < 8; i++) {
            float4 f0 = xr[2 * i], f1 = xr[2 * i + 1];
            x2 += f0.x * f0.x + f0.y * f0.y + f0.z * f0.z + f0.w * f0.w;
            x2 += f1.x * f1.x + f1.y * f1.y + f1.z * f1.z + f1.w * f1.w;
            uint4 u = make_uint4(pk(f0.x, f0.y), pk(f0.z, f0.w),
                                 pk(f1.x, f1.y), pk(f1.z, f1.w));
            *reinterpret_cast<uint4*>(sA + t * 128 + ((i ^ (t & 7)) << 4)) = u;
        }
        sx2[t] = x2;
    }

    const uint32_t sAb  = su32(sA);
    const uint32_t sBb0 = su32(sB[0]);
    const uint32_t sBb1 = su32(sB[1]);

    // ---- prefetch B chunk 0 ----
    {
        const char* src = reinterpret_cast<const char*>(g_codes_bf16);
#pragma unroll
        for (int i = 0; i < 4; i++) {
            int idx = t + i * TPB;                 // 512 x 16B = 8KB
            int n = idx >> 3, kb = idx & 7;
            CPASYNC16(sBb0 + n * 128 + ((kb ^ (n & 7)) << 4), src + idx * 16);
        }
        CPCOMMIT();
    }
    __syncthreads();

    // ---- A fragments (held in registers for the whole kernel) ----
    uint32_t Af[2][4][4];
    const int mbw = w * 32;
#pragma unroll
    for (int mt = 0; mt < 2; mt++)
#pragma unroll
        for (int k = 0; k < 4; k++) {
            int r  = mbw + mt * 16 + (L & 15);
            int kb = 2 * k + (L >> 4);
            uint32_t addr = sAb + r * 128 + ((kb ^ (r & 7)) << 4);
            LDSM4(Af[mt][k][0], Af[mt][k][1], Af[mt][k][2], Af[mt][k][3], addr);
        }

    const int g  = L >> 2;      // group id (row within 8)
    const int tc = L & 3;       // thread-in-group (col pair)
    float xs[4];
#pragma unroll
    for (int i = 0; i < 4; i++) xs[i] = sx2[mbw + g + i * 8];

    uint32_t kmin[4] = {0xFFFFFFFFu, 0xFFFFFFFFu, 0xFFFFFFFFu, 0xFFFFFFFFu};

    for (int ch = 0; ch < CHUNKS; ch++) {
        const uint32_t sBcur = (ch & 1) ? sBb1 : sBb0;

        // prefetch next chunk into the other buffer
        if (ch + 1 < CHUNKS) {
            const uint32_t sBnxt = (ch & 1) ? sBb0 : sBb1;
            const char* src = reinterpret_cast<const char*>(g_codes_bf16)
                              + (size_t)(ch + 1) * NC * D * 2;
#pragma unroll
            for (int i = 0; i < 4; i++) {
                int idx = t + i * TPB;
                int n = idx >> 3, kb = idx & 7;
                CPASYNC16(sBnxt + n * 128 + ((kb ^ (n & 7)) << 4), src + idx * 16);
            }
            CPCOMMIT();
            CPWAIT(1);
        } else {
            CPWAIT(0);
        }
        __syncthreads();       // B[ch] visible to all warps

        // ---- 64 HMMA: 2 m-tiles x 8 n-tiles x 4 k-steps ----
        float acc[2][8][4];
#pragma unroll
        for (int mt = 0; mt < 2; mt++)
#pragma unroll
            for (int nt = 0; nt < 8; nt++)
#pragma unroll
                for (int j = 0; j < 4; j++) acc[mt][nt][j] = 0.f;

#pragma unroll
        for (int k = 0; k < 4; k++) {
#pragma unroll
            for (int p = 0; p < 4; p++) {     // p covers n-tiles 2p, 2p+1
                uint32_t b0, b1, b2, b3;
                int rr = p * 16 + (L & 7) + ((L >> 4) << 3);
                int kb = 2 * k + ((L >> 3) & 1);
                uint32_t addr = sBcur + rr * 128 + ((kb ^ (rr & 7)) << 4);
                LDSM4(b0, b1, b2, b3, addr);
                MMA16816(acc[0][2 * p],     Af[0][k], b0, b1);
                MMA16816(acc[0][2 * p + 1], Af[0][k], b2, b3);
                MMA16816(acc[1][2 * p],     Af[1][k], b0, b1);
                MMA16816(acc[1][2 * p + 1], Af[1][k], b2, b3);
            }
        }

        // ---- epilogue: key = (bits(s') & ~0xFFF) | col, unsigned min ----
#pragma unroll
        for (int nt = 0; nt < 8; nt++) {
            const int cb = ch * NC + nt * 8 + tc * 2;
            float2 c2v = __ldg(reinterpret_cast<const float2*>(g_c2s + cb));
#pragma unroll
            for (int mt = 0; mt < 2; mt++) {
                const float* a = acc[mt][nt];
                uint32_t u0 = (__float_as_uint(fmaf(a[0], -2.f, c2v.x)) & 0xFFFFF000u) | (uint32_t)cb;
                uint32_t u1 = (__float_as_uint(fmaf(a[1], -2.f, c2v.y)) & 0xFFFFF000u) | (uint32_t)(cb + 1);
                uint32_t u2 = (__float_as_uint(fmaf(a[2], -2.f, c2v.x)) & 0xFFFFF000u) | (uint32_t)cb;
                uint32_t u3 = (__float_as_uint(fmaf(a[3], -2.f, c2v.y)) & 0xFFFFF000u) | (uint32_t)(cb + 1);
                kmin[mt * 2]     = min(kmin[mt * 2],     min(u0, u1));
                kmin[mt * 2 + 1] = min(kmin[mt * 2 + 1], min(u2, u3));
            }
        }
        __syncthreads();       // all reads of sB[ch&1] done before it is refilled
    }

    // ---- reduce across the 4 lanes of each row-group, then write ----
#pragma unroll
    for (int i = 0; i < 4; i++) {
        kmin[i] = min(kmin[i], __shfl_xor_sync(0xFFFFFFFFu, kmin[i], 1));
        kmin[i] = min(kmin[i], __shfl_xor_sync(0xFFFFFFFFu, kmin[i], 2));
    }
    if (tc == 0) {
#pragma unroll
        for (int i = 0; i < 4; i++) {
            uint32_t u = kmin[i];
            float sp = __uint_as_float(u & 0xFFFFF000u);
            float d2 = sp - 256.f + xs[i];
            int row = mbw + g + i * 8;
            out[(size_t)blockIdx.x * MT + row] = (d2 <= 0.1f) ? (float)(u & 0xFFFu) : -1.0f;
        }
    }
}

extern "C" void kernel_launch(void* const* d_in, const int* in_sizes, int n_in,
                              void* d_out, int out_size) {
    const float* x     = (const float*)d_in[0];
    const float* codes = (const float*)d_in[1];
    float*       out   = (float*)d_out;

    const int M     = in_sizes[1] / D;     // 4096
    const int nRows = in_sizes[0] / D;     // 65536

    prep_kernel<<<(M + 255) / 256, 256>>>(codes, M);
    nn_mma_kernel<<<nRows / MT, TPB>>>(x, out, M);
}

// round 5
// speedup vs baseline: 7.9561x; 1.1188x over previous
#include <cuda_runtime.h>
#include <cuda_bf16.h>
#include <cstdint>

#define D        64
#define MT       128         // x rows per CTA
#define NC       64          // codes per chunk
#define TPB      128
#define MAXM     4096
#define NSTAGE   3

__device__ __align__(16) __nv_bfloat16 g_codes_bf16[MAXM * D];
__device__ __align__(16) float         g_c2s[MAXM];   // ||c||^2 + 256

static __device__ __forceinline__ uint32_t pk(float lo, float hi) {
    uint32_t u;
    asm("cvt.rn.bf16x2.f32 %0, %1, %2;" : "=r"(u) : "f"(hi), "f"(lo));
    return u;
}
static __device__ __forceinline__ uint32_t su32(const void* p) {
    uint32_t a;
    asm("{ .reg .u64 t; cvta.to.shared.u64 t, %1; cvt.u32.u64 %0, t; }" : "=r"(a) : "l"(p));
    return a;
}

#define LDSM4(r0, r1, r2, r3, addr)                                                   \
    asm volatile("ldmatrix.sync.aligned.m8n8.x4.shared.b16 {%0,%1,%2,%3}, [%4];"      \
                 : "=r"(r0), "=r"(r1), "=r"(r2), "=r"(r3) : "r"(addr))

#define MMA16816(c, a, b0, b1)                                                        \
    asm volatile("mma.sync.aligned.m16n8k16.row.col.f32.bf16.bf16.f32 "               \
                 "{%0,%1,%2,%3},{%4,%5,%6,%7},{%8,%9},{%0,%1,%2,%3};"                 \
                 : "+f"((c)[0]), "+f"((c)[1]), "+f"((c)[2]), "+f"((c)[3])             \
                 : "r"((a)[0]), "r"((a)[1]), "r"((a)[2]), "r"((a)[3]),                \
                   "r"(b0), "r"(b1))

#define CPASYNC16(saddr, gptr)                                                        \
    asm volatile("cp.async.cg.shared.global [%0], [%1], 16;" :: "r"(saddr), "l"(gptr))
#define CPCOMMIT() asm volatile("cp.async.commit_group;")
#define CPWAIT(n)  asm volatile("cp.async.wait_group %0;" :: "n"(n))

// ---------------- prep: codes -> bf16 + (||c||^2 + 256) ----------------
__global__ void prep_kernel(const float* __restrict__ codes, int M) {
    int m = blockIdx.x * blockDim.x + threadIdx.x;
    if (m >= M) return;
    const float4* c = reinterpret_cast<const float4*>(codes + (size_t)m * D);
    uint2* dst = reinterpret_cast<uint2*>(g_codes_bf16 + (size_t)m * D);
    float s = 0.f;
#pragma unroll
    for (int i = 0; i < D / 4; i++) {
        float4 v = c[i];
        s += v.x * v.x + v.y * v.y + v.z * v.z + v.w * v.w;
        dst[i] = make_uint2(pk(v.x, v.y), pk(v.z, v.w));
    }
    g_c2s[m] = s + 256.f;    // shift keeps s' = c2s - 2 x.c strictly positive
}

// ---------------- main kernel ----------------
__global__ __launch_bounds__(TPB, 4) void nn_mma_kernel(
    const float* __restrict__ x, float* __restrict__ out, int M)
{
    __shared__ __align__(16) unsigned char sA[MT * 128];          // x tile bf16, swizzled
    __shared__ __align__(16) unsigned char sB[NSTAGE][NC * 128];  // code chunk ring
    __shared__ float sx2[MT];

    const int t = threadIdx.x;
    const int L = t & 31;
    const int w = t >> 5;
    const int CHUNKS = M / NC;

    // ---- stage x row t into sA (row t = 128B = 8 chunks of 16B, XOR swizzle) ----
    {
        const float4* xr = reinterpret_cast<const float4*>(
            x + ((size_t)blockIdx.x * MT + t) * D);
        float x2 = 0.f;
#pragma unroll
        for (int i = 0; i < 8; i++) {
            float4 f0 = xr[2 * i], f1 = xr[2 * i + 1];
            x2 += f0.x * f0.x + f0.y * f0.y + f0.z * f0.z + f0.w * f0.w;
            x2 += f1.x * f1.x + f1.y * f1.y + f1.z * f1.z + f1.w * f1.w;
            uint4 u = make_uint4(pk(f0.x, f0.y), pk(f0.z, f0.w),
                                 pk(f1.x, f1.y), pk(f1.z, f1.w));
            *reinterpret_cast<uint4*>(sA + t * 128 + ((i ^ (t & 7)) << 4)) = u;
        }
        sx2[t] = x2;
    }

    const uint32_t sAb = su32(sA);
    uint32_t sBb[NSTAGE];
#pragma unroll
    for (int s = 0; s < NSTAGE; s++) sBb[s] = su32(sB[s]);

    // B chunk prefetch: 512 x 16B = 8KB, 4 cp.async per thread
    auto prefetch = [&](int chunk) {
        const uint32_t dst = sBb[chunk % NSTAGE];
        const char* src = reinterpret_cast<const char*>(g_codes_bf16)
                          + (size_t)chunk * NC * D * 2;
#pragma unroll
        for (int i = 0; i < 4; i++) {
            int idx = t + i * TPB;
            int n = idx >> 3, kb = idx & 7;
            CPASYNC16(dst + n * 128 + ((kb ^ (n & 7)) << 4), src + idx * 16);
        }
        CPCOMMIT();
    };

    prefetch(0);
    prefetch(1);
    __syncthreads();           // sA + sx2 visible

    // ---- A fragments (held in registers for the whole kernel) ----
    uint32_t Af[2][4][4];
    const int mbw = w * 32;
#pragma unroll
    for (int mt = 0; mt < 2; mt++)
#pragma unroll
        for (int k = 0; k < 4; k++) {
            int r  = mbw + mt * 16 + (L & 15);
            int kb = 2 * k + (L >> 4);
            uint32_t addr = sAb + r * 128 + ((kb ^ (r & 7)) << 4);
            LDSM4(Af[mt][k][0], Af[mt][k][1], Af[mt][k][2], Af[mt][k][3], addr);
        }

    const int g  = L >> 2;      // row-in-group
    const int tc = L & 3;       // col-pair lane
    float xs[4];
#pragma unroll
    for (int i = 0; i < 4; i++) xs[i] = sx2[mbw + g + i * 8];

    uint32_t kmin[4] = {0xFFFFFFFFu, 0xFFFFFFFFu, 0xFFFFFFFFu, 0xFFFFFFFFu};

    for (int ch = 0; ch < CHUNKS; ch++) {
        if (ch == CHUNKS - 1) { CPWAIT(0); } else { CPWAIT(1); }   // buf[ch] arrived
        __syncthreads();        // all warps done with buf[(ch-1)%NSTAGE]; buf[ch] published
        if (ch + 2 < CHUNKS) prefetch(ch + 2);

        const uint32_t sBcur = sBb[ch % NSTAGE];

#pragma unroll
        for (int p = 0; p < 4; p++) {       // n-pair p covers n-tiles 2p, 2p+1
            float acc[2][2][4];
#pragma unroll
            for (int mt = 0; mt < 2; mt++)
#pragma unroll
                for (int j = 0; j < 2; j++)
#pragma unroll
                    for (int q = 0; q < 4; q++) acc[mt][j][q] = 0.f;

#pragma unroll
            for (int k = 0; k < 4; k++) {
                uint32_t b0, b1, b2, b3;
                int rr = p * 16 + (L & 7) + ((L >> 4) << 3);
                int kb = 2 * k + ((L >> 3) & 1);
                uint32_t addr = sBcur + rr * 128 + ((kb ^ (rr & 7)) << 4);
                LDSM4(b0, b1, b2, b3, addr);
                MMA16816(acc[0][0], Af[0][k], b0, b1);
                MMA16816(acc[0][1], Af[0][k], b2, b3);
                MMA16816(acc[1][0], Af[1][k], b0, b1);
                MMA16816(acc[1][1], Af[1][k], b2, b3);
            }

            // ---- fused epilogue for n-tiles 2p, 2p+1 ----
#pragma unroll
            for (int j = 0; j < 2; j++) {
                const int cb = ch * NC + (2 * p + j) * 8 + tc * 2;
                float2 c2v = __ldg(reinterpret_cast<const float2*>(g_c2s + cb));
#pragma unroll
                for (int mt = 0; mt < 2; mt++) {
                    const float* a = acc[mt][j];
                    uint32_t u0 = (__float_as_uint(fmaf(a[0], -2.f, c2v.x)) & 0xFFFFF000u) | (uint32_t)cb;
                    uint32_t u1 = (__float_as_uint(fmaf(a[1], -2.f, c2v.y)) & 0xFFFFF000u) | (uint32_t)(cb + 1);
                    uint32_t u2 = (__float_as_uint(fmaf(a[2], -2.f, c2v.x)) & 0xFFFFF000u) | (uint32_t)cb;
                    uint32_t u3 = (__float_as_uint(fmaf(a[3], -2.f, c2v.y)) & 0xFFFFF000u) | (uint32_t)(cb + 1);
                    kmin[mt * 2]     = min(kmin[mt * 2],     min(u0, u1));
                    kmin[mt * 2 + 1] = min(kmin[mt * 2 + 1], min(u2, u3));
                }
            }
        }
    }

    // ---- reduce across the 4 lanes of each row-group, then write ----
#pragma unroll
    for (int i = 0; i < 4; i++) {
        kmin[i] = min(kmin[i], __shfl_xor_sync(0xFFFFFFFFu, kmin[i], 1));
        kmin[i] = min(kmin[i], __shfl_xor_sync(0xFFFFFFFFu, kmin[i], 2));
    }
    if (tc == 0) {
#pragma unroll
        for (int i = 0; i < 4; i++) {
            uint32_t u = kmin[i];
            float sp = __uint_as_float(u & 0xFFFFF000u);
            float d2 = sp - 256.f + xs[i];
            int row = mbw + g + i * 8;
            out[(size_t)blockIdx.x * MT + row] = (d2 <= 0.1f) ? (float)(u & 0xFFFu) : -1.0f;
        }
    }
}

extern "C" void kernel_launch(void* const* d_in, const int* in_sizes, int n_in,
                              void* d_out, int out_size) {
    const float* x     = (const float*)d_in[0];
    const float* codes = (const float*)d_in[1];
    float*       out   = (float*)d_out;

    const int M     = in_sizes[1] / D;     // 4096
    const int nRows = in_sizes[0] / D;     // 65536

    prep_kernel<<<(M + 255) / 256, 256>>>(codes, M);
    nn_mma_kernel<<<nRows / MT, TPB>>>(x, out, M);
}

// round 6
// speedup vs baseline: 9.3973x; 1.1811x over previous
#include <cuda_runtime.h>
#include <cuda_fp16.h>
#include <cstdint>

#define D        64
#define MT       128         // x rows per CTA
#define NC       64          // codes per chunk
#define TPB      128
#define MAXM     4096
#define NSTAGE   3

__device__ __align__(16) __half g_codes_f16[MAXM * D];
__device__ __align__(16) __half g_c2h[MAXM];          // fp16(||c||^2 + 256)

static __device__ __forceinline__ uint32_t su32(const void* p) {
    uint32_t a;
    asm("{ .reg .u64 t; cvta.to.shared.u64 t, %1; cvt.u32.u64 %0, t; }" : "=r"(a) : "l"(p));
    return a;
}
static __device__ __forceinline__ uint32_t h2u(__half2 h) {
    return *reinterpret_cast<uint32_t*>(&h);
}
static __device__ __forceinline__ __half2 u2h(uint32_t u) {
    return *reinterpret_cast<__half2*>(&u);
}

#define LDSM4(r0, r1, r2, r3, addr)                                                   \
    asm volatile("ldmatrix.sync.aligned.m8n8.x4.shared.b16 {%0,%1,%2,%3}, [%4];"      \
                 : "=r"(r0), "=r"(r1), "=r"(r2), "=r"(r3) : "r"(addr))

// f16-accumulate HMMA (2x rate vs f32 accum)
#define MMA16816H(c0, c1, a, b0, b1)                                                  \
    asm volatile("mma.sync.aligned.m16n8k16.row.col.f16.f16.f16.f16 "                 \
                 "{%0,%1},{%2,%3,%4,%5},{%6,%7},{%0,%1};"                             \
                 : "+r"(c0), "+r"(c1)                                                 \
                 : "r"((a)[0]), "r"((a)[1]), "r"((a)[2]), "r"((a)[3]),                \
                   "r"(b0), "r"(b1))

#define CPASYNC16(saddr, gptr)                                                        \
    asm volatile("cp.async.cg.shared.global [%0], [%1], 16;" :: "r"(saddr), "l"(gptr))
#define CPCOMMIT() asm volatile("cp.async.commit_group;")
#define CPWAIT(n)  asm volatile("cp.async.wait_group %0;" :: "n"(n))

// ---------------- prep: codes -> fp16 + fp16(||c||^2 + 256) ----------------
__global__ void prep_kernel(const float* __restrict__ codes, int M) {
    int m = blockIdx.x * blockDim.x + threadIdx.x;
    if (m >= M) return;
    const float4* c = reinterpret_cast<const float4*>(codes + (size_t)m * D);
    __half2* dst = reinterpret_cast<__half2*>(g_codes_f16 + (size_t)m * D);
    float s = 0.f;
#pragma unroll
    for (int i = 0; i < D / 4; i++) {
        float4 v = c[i];
        s += v.x * v.x + v.y * v.y + v.z * v.z + v.w * v.w;
        dst[2 * i]     = __floats2half2_rn(v.x, v.y);
        dst[2 * i + 1] = __floats2half2_rn(v.z, v.w);
    }
    g_c2h[m] = __float2half_rn(s + 256.f);   // shift keeps s' > 0 (not required, but stable)
}

// ---------------- phase 1: min d^2 per row (fp16 tensor path) ----------------
__global__ __launch_bounds__(TPB, 4) void nn_mma_kernel(
    const float* __restrict__ x, float* __restrict__ out, int M)
{
    __shared__ __align__(16) unsigned char sA[MT * 128];          // x tile f16, swizzled
    __shared__ __align__(16) unsigned char sB[NSTAGE][NC * 128];  // code chunk ring
    __shared__ float sx2[MT];

    const int t = threadIdx.x;
    const int L = t & 31;
    const int w = t >> 5;
    const int CHUNKS = M / NC;

    // ---- stage x row t into sA (row = 128B = 8 x 16B, XOR swizzle), fp32 ||x||^2 ----
    {
        const float4* xr = reinterpret_cast<const float4*>(
            x + ((size_t)blockIdx.x * MT + t) * D);
        float x2 = 0.f;
#pragma unroll
        for (int i = 0; i < 8; i++) {
            float4 f0 = xr[2 * i], f1 = xr[2 * i + 1];
            x2 += f0.x * f0.x + f0.y * f0.y + f0.z * f0.z + f0.w * f0.w;
            x2 += f1.x * f1.x + f1.y * f1.y + f1.z * f1.z + f1.w * f1.w;
            uint4 u;
            u.x = h2u(__floats2half2_rn(f0.x, f0.y));
            u.y = h2u(__floats2half2_rn(f0.z, f0.w));
            u.z = h2u(__floats2half2_rn(f1.x, f1.y));
            u.w = h2u(__floats2half2_rn(f1.z, f1.w));
            *reinterpret_cast<uint4*>(sA + t * 128 + ((i ^ (t & 7)) << 4)) = u;
        }
        sx2[t] = x2;
    }

    const uint32_t sAb = su32(sA);
    uint32_t sBb[NSTAGE];
#pragma unroll
    for (int s = 0; s < NSTAGE; s++) sBb[s] = su32(sB[s]);

    auto prefetch = [&](int chunk) {
        const uint32_t dst = sBb[chunk % NSTAGE];
        const char* src = reinterpret_cast<const char*>(g_codes_f16)
                          + (size_t)chunk * NC * D * 2;
#pragma unroll
        for (int i = 0; i < 4; i++) {
            int idx = t + i * TPB;
            int n = idx >> 3, kb = idx & 7;
            CPASYNC16(dst + n * 128 + ((kb ^ (n & 7)) << 4), src + idx * 16);
        }
        CPCOMMIT();
    };

    prefetch(0);
    prefetch(1);
    __syncthreads();           // sA + sx2 visible

    // ---- A fragments (registers, whole kernel) ----
    uint32_t Af[2][4][4];
    const int mbw = w * 32;
#pragma unroll
    for (int mt = 0; mt < 2; mt++)
#pragma unroll
        for (int k = 0; k < 4; k++) {
            int r  = mbw + mt * 16 + (L & 15);
            int kb = 2 * k + (L >> 4);
            uint32_t addr = sAb + r * 128 + ((kb ^ (r & 7)) << 4);
            LDSM4(Af[mt][k][0], Af[mt][k][1], Af[mt][k][2], Af[mt][k][3], addr);
        }

    const int g  = L >> 2;      // row-in-group
    const int tc = L & 3;       // col-pair lane

    const __half2 neg2 = __floats2half2_rn(-2.f, -2.f);
    __half2 kmin[2][2];         // [mt][row-half], packed over the 2 cols this lane owns
#pragma unroll
    for (int a = 0; a < 2; a++)
#pragma unroll
        for (int b = 0; b < 2; b++) kmin[a][b] = __floats2half2_rn(65504.f, 65504.f);

    for (int ch = 0; ch < CHUNKS; ch++) {
        if (ch == CHUNKS - 1) { CPWAIT(0); } else { CPWAIT(1); }
        __syncthreads();        // buf[ch] published; all warps done with buf[ch-1]
        if (ch + 2 < CHUNKS) prefetch(ch + 2);

        const uint32_t sBcur = sBb[ch % NSTAGE];

#pragma unroll
        for (int p = 0; p < 4; p++) {       // n-pair p covers n-tiles 2p, 2p+1
            uint32_t acc[2][2][2];          // [mt][j][reg] f16x2 accum
#pragma unroll
            for (int mt = 0; mt < 2; mt++)
#pragma unroll
                for (int j = 0; j < 2; j++) { acc[mt][j][0] = 0u; acc[mt][j][1] = 0u; }

#pragma unroll
            for (int k = 0; k < 4; k++) {
                uint32_t b0, b1, b2, b3;
                int rr = p * 16 + (L & 7) + ((L >> 4) << 3);
                int kb = 2 * k + ((L >> 3) & 1);
                uint32_t addr = sBcur + rr * 128 + ((kb ^ (rr & 7)) << 4);
                LDSM4(b0, b1, b2, b3, addr);
                MMA16816H(acc[0][0][0], acc[0][0][1], Af[0][k], b0, b1);
                MMA16816H(acc[0][1][0], acc[0][1][1], Af[0][k], b2, b3);
                MMA16816H(acc[1][0][0], acc[1][0][1], Af[1][k], b0, b1);
                MMA16816H(acc[1][1][0], acc[1][1][1], Af[1][k], b2, b3);
            }

            // ---- epilogue: s' = c2 - 2*dot (half2), running half2 min ----
#pragma unroll
            for (int j = 0; j < 2; j++) {
                const int cb = ch * NC + (2 * p + j) * 8 + tc * 2;
                __half2 c2p = u2h(__ldg(reinterpret_cast<const uint32_t*>(g_c2h + cb)));
#pragma unroll
                for (int mt = 0; mt < 2; mt++) {
                    __half2 s0 = __hfma2(u2h(acc[mt][j][0]), neg2, c2p);
                    __half2 s1 = __hfma2(u2h(acc[mt][j][1]), neg2, c2p);
                    kmin[mt][0] = __hmin2(kmin[mt][0], s0);
                    kmin[mt][1] = __hmin2(kmin[mt][1], s1);
                }
            }
        }
    }

    // ---- reduce across 4 tc lanes + packed halves; write approx d^2 ----
#pragma unroll
    for (int mt = 0; mt < 2; mt++)
#pragma unroll
        for (int h = 0; h < 2; h++) {
            uint32_t k = h2u(kmin[mt][h]);
            k = h2u(__hmin2(u2h(k), u2h(__shfl_xor_sync(0xFFFFFFFFu, k, 1))));
            k = h2u(__hmin2(u2h(k), u2h(__shfl_xor_sync(0xFFFFFFFFu, k, 2))));
            if (tc == 0) {
                __half2 v = u2h(k);
                float smin = fminf(__half2float(__low2half(v)), __half2float(__high2half(v)));
                int row = mbw + mt * 16 + h * 8 + g;
                out[(size_t)blockIdx.x * MT + row] = smin + sx2[row] - 256.f;  // approx d^2
            }
        }
}

// ---------------- phase 2: threshold / (rare) exact rescan ----------------
__global__ void finalize_kernel(const float* __restrict__ x,
                                const float* __restrict__ codes,
                                float* __restrict__ out, int M)
{
    int row = blockIdx.x * blockDim.x + threadIdx.x;
    float d2a = out[row];
    if (d2a > 4.0f) {            // fp16 error << 3.9; true d2 certainly > 0.1
        out[row] = -1.0f;
        return;
    }
    // exact fp32 rescan of this row (first-argmin semantics)
    const float* xr = x + (size_t)row * D;
    float xv[D];
#pragma unroll
    for (int i = 0; i < D; i++) xv[i] = __ldg(xr + i);
    float best = 3.4e38f;
    int   bi = 0;
    for (int m = 0; m < M; m++) {
        const float* c = codes + (size_t)m * D;
        float s = 0.f;
#pragma unroll
        for (int i = 0; i < D; i++) {
            float dd = xv[i] - __ldg(c + i);
            s += dd * dd;
        }
        if (s < best) { best = s; bi = m; }
    }
    out[row] = (best <= 0.1f) ? (float)bi : -1.0f;
}

extern "C" void kernel_launch(void* const* d_in, const int* in_sizes, int n_in,
                              void* d_out, int out_size) {
    const float* x     = (const float*)d_in[0];
    const float* codes = (const float*)d_in[1];
    float*       out   = (float*)d_out;

    const int M     = in_sizes[1] / D;     // 4096
    const int nRows = in_sizes[0] / D;     // 65536

    prep_kernel<<<(M + 255) / 256, 256>>>(codes, M);
    nn_mma_kernel<<<nRows / MT, TPB>>>(x, out, M);
    finalize_kernel<<<nRows / 256, 256>>>(x, codes, out, M);
}

// round 7
// speedup vs baseline: 9.8892x; 1.0523x over previous
#include <cuda_runtime.h>
#include <cuda_fp16.h>
#include <cstdint>

#define D        64
#define MT       128         // x rows per CTA
#define NC       64          // codes per chunk
#define TPB      128
#define MAXM     4096

__device__ __align__(16) __half g_codes_f16[MAXM * D];
__device__ __align__(16) __half g_c2h[MAXM];          // fp16(||c||^2)

static __device__ __forceinline__ uint32_t su32(const void* p) {
    uint32_t a;
    asm("{ .reg .u64 t; cvta.to.shared.u64 t, %1; cvt.u32.u64 %0, t; }" : "=r"(a) : "l"(p));
    return a;
}
static __device__ __forceinline__ uint32_t h2u(__half2 h) {
    return *reinterpret_cast<uint32_t*>(&h);
}
static __device__ __forceinline__ __half2 u2h(uint32_t u) {
    return *reinterpret_cast<__half2*>(&u);
}

#define LDSM4(r0, r1, r2, r3, addr)                                                   \
    asm volatile("ldmatrix.sync.aligned.m8n8.x4.shared.b16 {%0,%1,%2,%3}, [%4];"      \
                 : "=r"(r0), "=r"(r1), "=r"(r2), "=r"(r3) : "r"(addr))

// f16-accumulate HMMA
#define MMA16816H(c0, c1, a, b0, b1)                                                  \
    asm volatile("mma.sync.aligned.m16n8k16.row.col.f16.f16.f16.f16 "                 \
                 "{%0,%1},{%2,%3,%4,%5},{%6,%7},{%0,%1};"                             \
                 : "+r"(c0), "+r"(c1)                                                 \
                 : "r"((a)[0]), "r"((a)[1]), "r"((a)[2]), "r"((a)[3]),                \
                   "r"(b0), "r"(b1))

#define CPASYNC16(saddr, gptr)                                                        \
    asm volatile("cp.async.cg.shared.global [%0], [%1], 16;" :: "r"(saddr), "l"(gptr))
#define CPCOMMIT() asm volatile("cp.async.commit_group;")
#define CPWAIT0()  asm volatile("cp.async.wait_group 0;")

// ---------------- prep: 16 threads per code row ----------------
__global__ void prep_kernel(const float* __restrict__ codes, int M) {
    int gid = blockIdx.x * blockDim.x + threadIdx.x;
    int m = gid >> 4, seg = gid & 15;
    if (m >= M) return;
    float4 v = __ldg(reinterpret_cast<const float4*>(codes + (size_t)m * D) + seg);
    float s = v.x * v.x + v.y * v.y + v.z * v.z + v.w * v.w;
    s += __shfl_xor_sync(0xFFFFFFFFu, s, 1);
    s += __shfl_xor_sync(0xFFFFFFFFu, s, 2);
    s += __shfl_xor_sync(0xFFFFFFFFu, s, 4);
    s += __shfl_xor_sync(0xFFFFFFFFu, s, 8);
    uint2 u;
    u.x = h2u(__floats2half2_rn(v.x, v.y));
    u.y = h2u(__floats2half2_rn(v.z, v.w));
    reinterpret_cast<uint2*>(g_codes_f16 + (size_t)m * D)[seg] = u;
    if (seg == 0) g_c2h[m] = __float2half_rn(s);
}

// ---------------- phase 1: min d^2 per row ----------------
__global__ __launch_bounds__(TPB, 4) void nn_mma_kernel(
    const float* __restrict__ x, float* __restrict__ out, int M)
{
    __shared__ __align__(16) unsigned char sA[MT * 128];      // 16 KB
    __shared__ __align__(16) unsigned char sB[4][NC * 128];   // 32 KB (2 pairs x 2 chunks)

    const int t = threadIdx.x;
    const int L = t & 31;
    const int w = t >> 5;
    const int NPAIR = (M / NC) / 2;     // 32

    // ---- stage x row t into sA; x2 kept in a register ----
    float x2 = 0.f;
    {
        const float4* xr = reinterpret_cast<const float4*>(
            x + ((size_t)blockIdx.x * MT + t) * D);
#pragma unroll
        for (int i = 0; i < 8; i++) {
            float4 f0 = xr[2 * i], f1 = xr[2 * i + 1];
            x2 += f0.x * f0.x + f0.y * f0.y + f0.z * f0.z + f0.w * f0.w;
            x2 += f1.x * f1.x + f1.y * f1.y + f1.z * f1.z + f1.w * f1.w;
            uint4 u;
            u.x = h2u(__floats2half2_rn(f0.x, f0.y));
            u.y = h2u(__floats2half2_rn(f0.z, f0.w));
            u.z = h2u(__floats2half2_rn(f1.x, f1.y));
            u.w = h2u(__floats2half2_rn(f1.z, f1.w));
            *reinterpret_cast<uint4*>(sA + t * 128 + ((i ^ (t & 7)) << 4)) = u;
        }
    }

    const uint32_t sAb = su32(sA);
    uint32_t sBb[4];
#pragma unroll
    for (int s = 0; s < 4; s++) sBb[s] = su32(sB[s]);

    // prefetch a PAIR of chunks (16 KB) into slot (q&1)
    auto prefetch_pair = [&](int q) {
        const int slot = (q & 1) * 2;
        const char* src = reinterpret_cast<const char*>(g_codes_f16)
                          + (size_t)q * 2 * NC * D * 2;
#pragma unroll
        for (int c = 0; c < 2; c++) {
            const uint32_t dst = sBb[slot + c];
            const char* s2 = src + (size_t)c * NC * D * 2;
#pragma unroll
            for (int i = 0; i < 4; i++) {
                int idx = t + i * TPB;
                int n = idx >> 3, kb = idx & 7;
                CPASYNC16(dst + n * 128 + ((kb ^ (n & 7)) << 4), s2 + idx * 16);
            }
        }
        CPCOMMIT();
    };

    prefetch_pair(0);
    __syncthreads();            // sA visible

    // ---- A fragments (registers, whole kernel) ----
    uint32_t Af[2][4][4];
    const int mbw = w * 32;
#pragma unroll
    for (int mt = 0; mt < 2; mt++)
#pragma unroll
        for (int k = 0; k < 4; k++) {
            int r  = mbw + mt * 16 + (L & 15);
            int kb = 2 * k + (L >> 4);
            uint32_t addr = sAb + r * 128 + ((kb ^ (r & 7)) << 4);
            LDSM4(Af[mt][k][0], Af[mt][k][1], Af[mt][k][2], Af[mt][k][3], addr);
        }

    const int g  = L >> 2;
    const int tc = L & 3;

    const __half2 neg2 = __floats2half2_rn(-2.f, -2.f);
    __half2 kmin[2][2];
#pragma unroll
    for (int a = 0; a < 2; a++)
#pragma unroll
        for (int b = 0; b < 2; b++) kmin[a][b] = __floats2half2_rn(65504.f, 65504.f);

    // B-fragment row/col (constant per lane)
    const int rrb = (L & 7) + ((L >> 4) << 3);

    for (int q = 0; q < NPAIR; q++) {
        CPWAIT0();              // pair q landed
        __syncthreads();        // published; all warps done with slot (q+1)&1
        if (q + 1 < NPAIR) prefetch_pair(q + 1);

        const uint32_t sB0 = sBb[(q & 1) * 2];
        const uint32_t sB1 = sBb[(q & 1) * 2 + 1];
        const int cb0 = (2 * q) * NC;
        const int cb1 = (2 * q + 1) * NC;

#pragma unroll
        for (int p = 0; p < 4; p++) {
            // hoisted c2 loads (hidden under the MMAs below)
            uint32_t c2a0 = __ldg(reinterpret_cast<const uint32_t*>(g_c2h + cb0 + (2 * p) * 8 + tc * 2));
            uint32_t c2a1 = __ldg(reinterpret_cast<const uint32_t*>(g_c2h + cb0 + (2 * p + 1) * 8 + tc * 2));
            uint32_t c2b0 = __ldg(reinterpret_cast<const uint32_t*>(g_c2h + cb1 + (2 * p) * 8 + tc * 2));
            uint32_t c2b1 = __ldg(reinterpret_cast<const uint32_t*>(g_c2h + cb1 + (2 * p + 1) * 8 + tc * 2));

            uint32_t acc0[2][2][2], acc1[2][2][2];
#pragma unroll
            for (int mt = 0; mt < 2; mt++)
#pragma unroll
                for (int j = 0; j < 2; j++) {
                    acc0[mt][j][0] = 0u; acc0[mt][j][1] = 0u;
                    acc1[mt][j][0] = 0u; acc1[mt][j][1] = 0u;
                }

            const int rr = p * 16 + rrb;
#pragma unroll
            for (int k = 0; k < 4; k++) {
                const int kb = 2 * k + ((L >> 3) & 1);
                const uint32_t off = rr * 128 + ((kb ^ (rr & 7)) << 4);
                uint32_t a0, a1, a2, a3, b0, b1, b2, b3;
                LDSM4(a0, a1, a2, a3, sB0 + off);
                LDSM4(b0, b1, b2, b3, sB1 + off);
                MMA16816H(acc0[0][0][0], acc0[0][0][1], Af[0][k], a0, a1);
                MMA16816H(acc0[0][1][0], acc0[0][1][1], Af[0][k], a2, a3);
                MMA16816H(acc0[1][0][0], acc0[1][0][1], Af[1][k], a0, a1);
                MMA16816H(acc0[1][1][0], acc0[1][1][1], Af[1][k], a2, a3);
                MMA16816H(acc1[0][0][0], acc1[0][0][1], Af[0][k], b0, b1);
                MMA16816H(acc1[0][1][0], acc1[0][1][1], Af[0][k], b2, b3);
                MMA16816H(acc1[1][0][0], acc1[1][0][1], Af[1][k], b0, b1);
                MMA16816H(acc1[1][1][0], acc1[1][1][1], Af[1][k], b2, b3);
            }

            // ---- epilogue: s = c2 - 2*dot, running half2 min ----
#pragma unroll
            for (int mt = 0; mt < 2; mt++) {
                kmin[mt][0] = __hmin2(kmin[mt][0], __hfma2(u2h(acc0[mt][0][0]), neg2, u2h(c2a0)));
                kmin[mt][1] = __hmin2(kmin[mt][1], __hfma2(u2h(acc0[mt][0][1]), neg2, u2h(c2a0)));
                kmin[mt][0] = __hmin2(kmin[mt][0], __hfma2(u2h(acc0[mt][1][0]), neg2, u2h(c2a1)));
                kmin[mt][1] = __hmin2(kmin[mt][1], __hfma2(u2h(acc0[mt][1][1]), neg2, u2h(c2a1)));
                kmin[mt][0] = __hmin2(kmin[mt][0], __hfma2(u2h(acc1[mt][0][0]), neg2, u2h(c2b0)));
                kmin[mt][1] = __hmin2(kmin[mt][1], __hfma2(u2h(acc1[mt][0][1]), neg2, u2h(c2b0)));
                kmin[mt][0] = __hmin2(kmin[mt][0], __hfma2(u2h(acc1[mt][1][0]), neg2, u2h(c2b1)));
                kmin[mt][1] = __hmin2(kmin[mt][1], __hfma2(u2h(acc1[mt][1][1]), neg2, u2h(c2b1)));
            }
        }
    }

    // ---- reduce across 4 tc lanes, fetch x2 via shfl, write approx d^2 ----
#pragma unroll
    for (int mt = 0; mt < 2; mt++)
#pragma unroll
        for (int h = 0; h < 2; h++) {
            uint32_t k = h2u(kmin[mt][h]);
            k = h2u(__hmin2(u2h(k), u2h(__shfl_xor_sync(0xFFFFFFFFu, k, 1))));
            k = h2u(__hmin2(u2h(k), u2h(__shfl_xor_sync(0xFFFFFFFFu, k, 2))));
            // row owner (thread = row) lives in this same warp at lane mt*16+h*8+g... 
            // rows mbw..mbw+31 are threads w*32..w*32+31 -> lane = mt*16 + h*8 + g
            float x2row = __shfl_sync(0xFFFFFFFFu, x2, mt * 16 + h * 8 + g);
            if (tc == 0) {
                __half2 v = u2h(k);
                float smin = fminf(__half2float(__low2half(v)), __half2float(__high2half(v)));
                int row = mbw + mt * 16 + h * 8 + g;
                out[(size_t)blockIdx.x * MT + row] = smin + x2row;   // approx d^2
            }
        }
}

// ---------------- phase 2: threshold / (rare) exact rescan ----------------
__global__ void finalize_kernel(const float* __restrict__ x,
                                const float* __restrict__ codes,
                                float* __restrict__ out, int M)
{
    int row = blockIdx.x * blockDim.x + threadIdx.x;
    float d2a = out[row];
    if (d2a > 4.0f) {            // fp16 error << 3.9; true d2 certainly > 0.1
        out[row] = -1.0f;
        return;
    }
    const float* xr = x + (size_t)row * D;
    float xv[D];
#pragma unroll
    for (int i = 0; i < D; i++) xv[i] = __ldg(xr + i);
    float best = 3.4e38f;
    int   bi = 0;
    for (int m = 0; m < M; m++) {
        const float* c = codes + (size_t)m * D;
        float s = 0.f;
#pragma unroll
        for (int i = 0; i < D; i++) {
            float dd = xv[i] - __ldg(c + i);
            s += dd * dd;
        }
        if (s < best) { best = s; bi = m; }
    }
    out[row] = (best <= 0.1f) ? (float)bi : -1.0f;
}

extern "C" void kernel_launch(void* const* d_in, const int* in_sizes, int n_in,
                              void* d_out, int out_size) {
    const float* x     = (const float*)d_in[0];
    const float* codes = (const float*)d_in[1];
    float*       out   = (float*)d_out;

    const int M     = in_sizes[1] / D;     // 4096
    const int nRows = in_sizes[0] / D;     // 65536

    prep_kernel<<<(M * 16) / 256, 256>>>(codes, M);
    nn_mma_kernel<<<nRows / MT, TPB>>>(x, out, M);
    finalize_kernel<<<nRows / 256, 256>>>(x, codes, out, M);
}

// round 8
// speedup vs baseline: 10.1684x; 1.0282x over previous
#include <cuda_runtime.h>
#include <cuda_fp16.h>
#include <cstdint>

#define D        64
#define MT       128         // x rows per CTA
#define NC       64          // codes per chunk
#define TPB      128
#define MAXM     4096

__device__ __align__(16) __half g_codes_f16[MAXM * D];
__device__ __align__(16) __half g_c2h[MAXM];          // fp16(-||c||^2 / 2)

static __device__ __forceinline__ uint32_t su32(const void* p) {
    uint32_t a;
    asm("{ .reg .u64 t; cvta.to.shared.u64 t, %1; cvt.u32.u64 %0, t; }" : "=r"(a) : "l"(p));
    return a;
}
static __device__ __forceinline__ uint32_t h2u(__half2 h) {
    return *reinterpret_cast<uint32_t*>(&h);
}
static __device__ __forceinline__ __half2 u2h(uint32_t u) {
    return *reinterpret_cast<__half2*>(&u);
}

#define LDSM4(r0, r1, r2, r3, addr)                                                   \
    asm volatile("ldmatrix.sync.aligned.m8n8.x4.shared.b16 {%0,%1,%2,%3}, [%4];"      \
                 : "=r"(r0), "=r"(r1), "=r"(r2), "=r"(r3) : "r"(addr))

// f16-accumulate HMMA
#define MMA16816H(c0, c1, a, b0, b1)                                                  \
    asm volatile("mma.sync.aligned.m16n8k16.row.col.f16.f16.f16.f16 "                 \
                 "{%0,%1},{%2,%3,%4,%5},{%6,%7},{%0,%1};"                             \
                 : "+r"(c0), "+r"(c1)                                                 \
                 : "r"((a)[0]), "r"((a)[1]), "r"((a)[2]), "r"((a)[3]),                \
                   "r"(b0), "r"(b1))

#define CPASYNC16(saddr, gptr)                                                        \
    asm volatile("cp.async.cg.shared.global [%0], [%1], 16;" :: "r"(saddr), "l"(gptr))
#define CPCOMMIT() asm volatile("cp.async.commit_group;")
#define CPWAIT(n)  asm volatile("cp.async.wait_group %0;" :: "n"(n))

// ---------------- prep: 16 threads per code row ----------------
__global__ void prep_kernel(const float* __restrict__ codes, int M) {
    int gid = blockIdx.x * blockDim.x + threadIdx.x;
    int m = gid >> 4, seg = gid & 15;
    if (m >= M) return;
    float4 v = __ldg(reinterpret_cast<const float4*>(codes + (size_t)m * D) + seg);
    float s = v.x * v.x + v.y * v.y + v.z * v.z + v.w * v.w;
    s += __shfl_xor_sync(0xFFFFFFFFu, s, 1);
    s += __shfl_xor_sync(0xFFFFFFFFu, s, 2);
    s += __shfl_xor_sync(0xFFFFFFFFu, s, 4);
    s += __shfl_xor_sync(0xFFFFFFFFu, s, 8);
    uint2 u;
    u.x = h2u(__floats2half2_rn(v.x, v.y));
    u.y = h2u(__floats2half2_rn(v.z, v.w));
    reinterpret_cast<uint2*>(g_codes_f16 + (size_t)m * D)[seg] = u;
    if (seg == 0) g_c2h[m] = __float2half_rn(-0.5f * s);   // acc-init form
}

// ---------------- phase 1: max(dot - c^2/2) per row ----------------
__global__ __launch_bounds__(TPB, 4) void nn_mma_kernel(
    const float* __restrict__ x, float* __restrict__ out, int M)
{
    // 48KB: 6 B-chunk slots of 8KB; slots 4,5 double as the transient A staging area
    __shared__ __align__(128) unsigned char sm[6 * NC * 128];

    const int t = threadIdx.x;
    const int L = t & 31;
    const int w = t >> 5;
    const int NPAIR = (M / NC) / 2;     // 32

    // ---- stage x row t into A area (slots 4-5); x2 in a register ----
    float x2 = 0.f;
    {
        const float4* xr = reinterpret_cast<const float4*>(
            x + ((size_t)blockIdx.x * MT + t) * D);
        unsigned char* sA = sm + 4 * NC * 128;
#pragma unroll
        for (int i = 0; i < 8; i++) {
            float4 f0 = xr[2 * i], f1 = xr[2 * i + 1];
            x2 += f0.x * f0.x + f0.y * f0.y + f0.z * f0.z + f0.w * f0.w;
            x2 += f1.x * f1.x + f1.y * f1.y + f1.z * f1.z + f1.w * f1.w;
            uint4 u;
            u.x = h2u(__floats2half2_rn(f0.x, f0.y));
            u.y = h2u(__floats2half2_rn(f0.z, f0.w));
            u.z = h2u(__floats2half2_rn(f1.x, f1.y));
            u.w = h2u(__floats2half2_rn(f1.z, f1.w));
            *reinterpret_cast<uint4*>(sA + t * 128 + ((i ^ (t & 7)) << 4)) = u;
        }
    }

    uint32_t sC[6];
#pragma unroll
    for (int s = 0; s < 6; s++) sC[s] = su32(sm + s * NC * 128);

    // prefetch a PAIR of chunks (16 KB) into ring slot q%3 (chunks slot*2, slot*2+1)
    auto prefetch_pair = [&](int q) {
        const int slot = (q % 3) * 2;
        const char* src = reinterpret_cast<const char*>(g_codes_f16)
                          + (size_t)q * 2 * NC * D * 2;
#pragma unroll
        for (int c = 0; c < 2; c++) {
            const uint32_t dst = sC[slot + c];
            const char* s2 = src + (size_t)c * NC * D * 2;
#pragma unroll
            for (int i = 0; i < 4; i++) {
                int idx = t + i * TPB;
                int n = idx >> 3, kb = idx & 7;
                CPASYNC16(dst + n * 128 + ((kb ^ (n & 7)) << 4), s2 + idx * 16);
            }
        }
        CPCOMMIT();
    };

    prefetch_pair(0);          // slot 0 (chunks 0,1)
    prefetch_pair(1);          // slot 1 (chunks 2,3)
    __syncthreads();           // A staging visible

    // ---- A fragments from slots 4-5 (registers for whole kernel) ----
    uint32_t Af[2][4][4];
    const uint32_t sAb = sC[4];
    const int mbw = w * 32;
#pragma unroll
    for (int mt = 0; mt < 2; mt++)
#pragma unroll
        for (int k = 0; k < 4; k++) {
            int r  = mbw + mt * 16 + (L & 15);
            int kb = 2 * k + (L >> 4);
            uint32_t addr = sAb + r * 128 + ((kb ^ (r & 7)) << 4);
            LDSM4(Af[mt][k][0], Af[mt][k][1], Af[mt][k][2], Af[mt][k][3], addr);
        }

    const int g  = L >> 2;
    const int tc = L & 3;
    const int rrb = (L & 7) + ((L >> 4) << 3);
    const int kbb = (L >> 3) & 1;

    __half2 kmax[2][2];
#pragma unroll
    for (int a = 0; a < 2; a++)
#pragma unroll
        for (int b = 0; b < 2; b++) kmax[a][b] = __floats2half2_rn(-65504.f, -65504.f);

    for (int q = 0; q < NPAIR; q++) {
        if (q >= NPAIR - 1) { CPWAIT(0); } else { CPWAIT(1); }   // pair q landed
        __syncthreads();        // all warps done with the slot pair (q+2) will overwrite
        if (q + 2 < NPAIR) prefetch_pair(q + 2);

        const int slot = (q % 3) * 2;
        const uint32_t sB0 = sC[slot];
        const uint32_t sB1 = sC[slot + 1];
        const int cb0 = (2 * q) * NC;
        const int cb1 = (2 * q + 1) * NC;

#pragma unroll
        for (int p = 0; p < 4; p++) {
            // c2 init values (packed -c^2/2 for this lane's 2 columns)
            uint32_t c2a0 = __ldg(reinterpret_cast<const uint32_t*>(g_c2h + cb0 + (2 * p) * 8 + tc * 2));
            uint32_t c2a1 = __ldg(reinterpret_cast<const uint32_t*>(g_c2h + cb0 + (2 * p + 1) * 8 + tc * 2));
            uint32_t c2b0 = __ldg(reinterpret_cast<const uint32_t*>(g_c2h + cb1 + (2 * p) * 8 + tc * 2));
            uint32_t c2b1 = __ldg(reinterpret_cast<const uint32_t*>(g_c2h + cb1 + (2 * p + 1) * 8 + tc * 2));

            uint32_t acc0[2][2][2], acc1[2][2][2];
#pragma unroll
            for (int mt = 0; mt < 2; mt++) {
                acc0[mt][0][0] = c2a0; acc0[mt][0][1] = c2a0;
                acc0[mt][1][0] = c2a1; acc0[mt][1][1] = c2a1;
                acc1[mt][0][0] = c2b0; acc1[mt][0][1] = c2b0;
                acc1[mt][1][0] = c2b1; acc1[mt][1][1] = c2b1;
            }

            const int rr = p * 16 + rrb;
            // LDSM double buffer across k
            uint32_t f[2][8];
            {
                const uint32_t off = rr * 128 + (((0 ^ 0) + kbb ^ (rr & 7)) << 4);
                const uint32_t o0 = rr * 128 + (((2 * 0 + kbb) ^ (rr & 7)) << 4);
                (void)off;
                LDSM4(f[0][0], f[0][1], f[0][2], f[0][3], sB0 + o0);
                LDSM4(f[0][4], f[0][5], f[0][6], f[0][7], sB1 + o0);
            }
#pragma unroll
            for (int k = 0; k < 4; k++) {
                if (k < 3) {
                    const uint32_t on = rr * 128 + (((2 * (k + 1) + kbb) ^ (rr & 7)) << 4);
                    LDSM4(f[(k + 1) & 1][0], f[(k + 1) & 1][1], f[(k + 1) & 1][2], f[(k + 1) & 1][3], sB0 + on);
                    LDSM4(f[(k + 1) & 1][4], f[(k + 1) & 1][5], f[(k + 1) & 1][6], f[(k + 1) & 1][7], sB1 + on);
                }
                const uint32_t* b = f[k & 1];
                MMA16816H(acc0[0][0][0], acc0[0][0][1], Af[0][k], b[0], b[1]);
                MMA16816H(acc0[0][1][0], acc0[0][1][1], Af[0][k], b[2], b[3]);
                MMA16816H(acc0[1][0][0], acc0[1][0][1], Af[1][k], b[0], b[1]);
                MMA16816H(acc0[1][1][0], acc0[1][1][1], Af[1][k], b[2], b[3]);
                MMA16816H(acc1[0][0][0], acc1[0][0][1], Af[0][k], b[4], b[5]);
                MMA16816H(acc1[0][1][0], acc1[0][1][1], Af[0][k], b[6], b[7]);
                MMA16816H(acc1[1][0][0], acc1[1][0][1], Af[1][k], b[4], b[5]);
                MMA16816H(acc1[1][1][0], acc1[1][1][1], Af[1][k], b[6], b[7]);
            }

            // ---- epilogue: pure HMAX2 (c2 already inside acc) ----
#pragma unroll
            for (int mt = 0; mt < 2; mt++) {
                kmax[mt][0] = __hmax2(kmax[mt][0], u2h(acc0[mt][0][0]));
                kmax[mt][1] = __hmax2(kmax[mt][1], u2h(acc0[mt][0][1]));
                kmax[mt][0] = __hmax2(kmax[mt][0], u2h(acc0[mt][1][0]));
                kmax[mt][1] = __hmax2(kmax[mt][1], u2h(acc0[mt][1][1]));
                kmax[mt][0] = __hmax2(kmax[mt][0], u2h(acc1[mt][0][0]));
                kmax[mt][1] = __hmax2(kmax[mt][1], u2h(acc1[mt][0][1]));
                kmax[mt][0] = __hmax2(kmax[mt][0], u2h(acc1[mt][1][0]));
                kmax[mt][1] = __hmax2(kmax[mt][1], u2h(acc1[mt][1][1]));
            }
        }
    }

    // ---- reduce across 4 tc lanes; min d^2 = x^2 - 2*max(acc) ----
#pragma unroll
    for (int mt = 0; mt < 2; mt++)
#pragma unroll
        for (int h = 0; h < 2; h++) {
            uint32_t k = h2u(kmax[mt][h]);
            k = h2u(__hmax2(u2h(k), u2h(__shfl_xor_sync(0xFFFFFFFFu, k, 1))));
            k = h2u(__hmax2(u2h(k), u2h(__shfl_xor_sync(0xFFFFFFFFu, k, 2))));
            float x2row = __shfl_sync(0xFFFFFFFFu, x2, mt * 16 + h * 8 + g);
            if (tc == 0) {
                __half2 v = u2h(k);
                float smax = fmaxf(__half2float(__low2half(v)), __half2float(__high2half(v)));
                int row = mbw + mt * 16 + h * 8 + g;
                out[(size_t)blockIdx.x * MT + row] = fmaf(smax, -2.f, x2row);  // approx min d^2
            }
        }
}

// ---------------- phase 2: threshold / (rare) exact rescan ----------------
__global__ void finalize_kernel(const float* __restrict__ x,
                                const float* __restrict__ codes,
                                float* __restrict__ out, int M)
{
    int row = blockIdx.x * blockDim.x + threadIdx.x;
    float d2a = out[row];
    if (d2a > 4.0f) {            // fp16 error << 3.9; true d2 certainly > 0.1
        out[row] = -1.0f;
        return;
    }
    const float* xr = x + (size_t)row * D;
    float xv[D];
#pragma unroll
    for (int i = 0; i < D; i++) xv[i] = __ldg(xr + i);
    float best = 3.4e38f;
    int   bi = 0;
    for (int m = 0; m < M; m++) {
        const float* c = codes + (size_t)m * D;
        float s = 0.f;
#pragma unroll
        for (int i = 0; i < D; i++) {
            float dd = xv[i] - __ldg(c + i);
            s += dd * dd;
        }
        if (s < best) { best = s; bi = m; }
    }
    out[row] = (best <= 0.1f) ? (float)bi : -1.0f;
}

extern "C" void kernel_launch(void* const* d_in, const int* in_sizes, int n_in,
                              void* d_out, int out_size) {
    const float* x     = (const float*)d_in[0];
    const float* codes = (const float*)d_in[1];
    float*       out   = (float*)d_out;

    const int M     = in_sizes[1] / D;     // 4096
    const int nRows = in_sizes[0] / D;     // 65536

    prep_kernel<<<(M * 16) / 256, 256>>>(codes, M);
    nn_mma_kernel<<<nRows / MT, TPB>>>(x, out, M);
    finalize_kernel<<<nRows / 256, 256>>>(x, codes, out, M);
}